// round 16
// baseline (speedup 1.0000x reference)
#include <cuda_runtime.h>
#include <cuda_fp16.h>
#include <mma.h>
#include <math.h>
#include <stdint.h>

#define BB   4
#define NN   2048
#define DIMM 1024
#define HID  4096
#define NE   16
#define CAP  256
#define NTOK (BB*NN)          // 8192 tokens
#define NSLOT (NE*BB*CAP)     // 16384 expert slot rows
#define FLT_MIN_NORM 1.17549435e-38f
#define EXP_FTZ_CUT  (-87.336544f)

using namespace nvcuda;

// ------------------------- scratch (device globals) -------------------------
__device__ float  g_probs[NTOK*NE];
__device__ int    g_e1[NTOK], g_e2[NTOK];
__device__ float  g_g1[NTOK], g_g2[NTOK];
__device__ int    g_slot1[NTOK], g_slot2[NTOK];
__device__ int    g_slot_token[NSLOT];
__device__ int    g_cnt_total[BB*NE];
__device__ float  g_part_loss[BB*NE];
__device__ __half g_einh [(size_t)NSLOT*DIMM];       // 32 MB
__device__ __half g_hidh [(size_t)NSLOT*HID];        // 128 MB
__device__ __half g_w1h  [(size_t)NE*DIMM*HID];      // 128 MB
__device__ __half g_w2h  [(size_t)NE*HID*DIMM];      // 128 MB
__device__ float  g_pout [(size_t)2*NSLOT*DIMM];     // 128 MB (split-K partials)

// ------------------------- async-copy helpers --------------------------------
__device__ __forceinline__ uint32_t s2u(const void* p) {
    uint32_t a;
    asm("{ .reg .u64 t; cvta.to.shared.u64 t, %1; cvt.u32.u64 %0, t; }"
        : "=r"(a) : "l"(p));
    return a;
}
#define CP16(dst, src) \
    asm volatile("cp.async.cg.shared.global [%0], [%1], 16;" \
                 :: "r"(dst), "l"(src) : "memory")
#define CP_COMMIT() asm volatile("cp.async.commit_group;" ::: "memory")
#define CP_WAIT1()  asm volatile("cp.async.wait_group 1;" ::: "memory")

// -------------------- gating + fused w1 conversion ---------------------------
// blocks [0, NTOK)          : gating (GOLDEN FTZ pipeline)
// blocks [NTOK, NTOK+4096)  : w1 fp32 -> fp16 (overlaps gating's latency stalls)
__global__ void gating_wconv1_kernel(const float* __restrict__ x,
                                     const float* __restrict__ wg,
                                     const float4* __restrict__ w1src, int n4) {
    if (blockIdx.x >= NTOK) {
        uint2* __restrict__ dst = (uint2*)g_w1h;
        int i = (blockIdx.x - NTOK) * blockDim.x + threadIdx.x;
        int stride = 4096 * blockDim.x;
        for (; i < n4; i += stride) {
            float4 v = w1src[i];
            __half2 h0 = __floats2half2_rn(v.x, v.y);
            __half2 h1 = __floats2half2_rn(v.z, v.w);
            uint2 o; o.x = *(uint32_t*)&h0; o.y = *(uint32_t*)&h1;
            dst[i] = o;
        }
        return;
    }

    int tok  = blockIdx.x;
    int wid  = threadIdx.x >> 5;        // expert
    int lane = threadIdx.x & 31;
    const float* xr = x + (size_t)tok * DIMM;

    float acc = 0.f;
    #pragma unroll 8
    for (int d = lane; d < DIMM; d += 32)
        acc = fmaf(xr[d], wg[d * NE + wid], acc);
    #pragma unroll
    for (int o = 16; o; o >>= 1) acc += __shfl_xor_sync(0xffffffffu, acc, o);

    __shared__ float lg[NE];
    if (lane == 0) lg[wid] = acc;
    __syncthreads();

    if (threadIdx.x == 0) {
        float l[NE], p[NE];
        #pragma unroll
        for (int i = 0; i < NE; i++) l[i] = lg[i];

        float m = l[0];
        #pragma unroll
        for (int i = 1; i < NE; i++) m = fmaxf(m, l[i]);
        float s = 0.f;
        #pragma unroll
        for (int i = 0; i < NE; i++) {
            float t = l[i] - m;
            float pe = (t < EXP_FTZ_CUT) ? 0.f : expf(t);   // FTZ exp
            p[i] = pe; s = s + pe;
        }
        #pragma unroll
        for (int i = 0; i < NE; i++) {
            float q = p[i] / s;
            if (q < FLT_MIN_NORM) q = 0.f;                  // FTZ divide
            p[i] = q;
        }

        int i1 = 0; float p1 = p[0];
        #pragma unroll
        for (int i = 1; i < NE; i++) if (p[i] > p1) { p1 = p[i]; i1 = i; }
        float gw[NE];
        #pragma unroll
        for (int i = 0; i < NE; i++) gw[i] = (i == i1) ? 0.f : p[i];
        int i2 = 0; float p2v = gw[0];
        #pragma unroll
        for (int i = 1; i < NE; i++) if (gw[i] > p2v) { p2v = gw[i]; i2 = i; }

        float den = p1 + p2v + 1e-9f;
        g_e1[tok] = i1; g_e2[tok] = i2;
        g_g1[tok] = p1 / den; g_g2[tok] = p2v / den;
        #pragma unroll
        for (int i = 0; i < NE; i++) g_probs[tok * NE + i] = p[i];
    }
}

// ---------------- capacity / assign (slot-segment clear fused in) ------------
__global__ void assign_kernel() {
    const int T = 256, TPT = NN / T;
    int b = blockIdx.x / NE, e = blockIdx.x % NE;
    int t = threadIdx.x;
    __shared__ int s[T];

    g_slot_token[(e * BB + b) * CAP + t] = -1;
    __syncthreads();

    int flag[TPT], loc[TPT]; int c = 0;
    #pragma unroll
    for (int i = 0; i < TPT; i++) {
        int n = t * TPT + i;
        int f = (g_e1[b * NN + n] == e);
        flag[i] = f; loc[i] = c; c += f;
    }
    s[t] = c; __syncthreads();
    for (int off = 1; off < T; off <<= 1) {
        int v = (t >= off) ? s[t - off] : 0;
        __syncthreads(); s[t] += v; __syncthreads();
    }
    int total = s[T - 1];
    int excl  = s[t] - c;
    #pragma unroll
    for (int i = 0; i < TPT; i++) {
        if (flag[i]) {
            int n = t * TPT + i, gi = b * NN + n;
            int pos = excl + loc[i];
            if (pos < CAP) {
                int slot = (e * BB + b) * CAP + pos;
                g_slot1[gi] = slot;
                g_slot_token[slot] = gi;
            } else g_slot1[gi] = -1;
        }
    }
    if (t == 0) g_cnt_total[b * NE + e] = total;
    int kept1 = total < CAP ? total : CAP;
    __syncthreads();

    c = 0;
    #pragma unroll
    for (int i = 0; i < TPT; i++) {
        int n = t * TPT + i;
        int f = (g_e2[b * NN + n] == e);
        flag[i] = f; loc[i] = c; c += f;
    }
    s[t] = c; __syncthreads();
    for (int off = 1; off < T; off <<= 1) {
        int v = (t >= off) ? s[t - off] : 0;
        __syncthreads(); s[t] += v; __syncthreads();
    }
    excl = s[t] - c;
    #pragma unroll
    for (int i = 0; i < TPT; i++) {
        if (flag[i]) {
            int n = t * TPT + i, gi = b * NN + n;
            int pos = excl + loc[i] + kept1;
            if (pos < CAP) {
                int slot = (e * BB + b) * CAP + pos;
                g_slot2[gi] = slot;
                g_slot_token[slot] = gi;
            } else g_slot2[gi] = -1;
        }
    }
}

// ------------------------------- gather (fp32 -> fp16) -----------------------
__global__ void gather_kernel(const float* __restrict__ x) {
    int row = blockIdx.x;
    int tok = g_slot_token[row];
    uint2* dst = (uint2*)(g_einh + (size_t)row * DIMM);
    int t = threadIdx.x;
    if (tok >= 0) {
        float4 v = ((const float4*)(x + (size_t)tok * DIMM))[t];
        __half2 h0 = __floats2half2_rn(v.x, v.y);
        __half2 h1 = __floats2half2_rn(v.z, v.w);
        uint2 o; o.x = *(uint32_t*)&h0; o.y = *(uint32_t*)&h1;
        dst[t] = o;
    } else {
        dst[t] = make_uint2(0u, 0u);
    }
}

__device__ __forceinline__ float gelu_exact(float v) {
    return 0.5f * v * (1.f + erff(v * 0.70710678118654752f));
}

// ---------------- GEMM1: 128x128x64, 3-stage, +fused wconv2 ------------------
__global__ void __launch_bounds__(256, 2) hgemm1(const float* __restrict__ bias,
                                                 const float4* __restrict__ w2src,
                                                 int n4) {
    constexpr int KDIM = DIMM, NDIM = HID;
    constexpr int GRIDX = NDIM / 128;
    constexpr int NGEMM = GRIDX * (NSLOT / 128);

    if (blockIdx.x >= NGEMM) {
        uint2* __restrict__ dst = (uint2*)g_w2h;
        int i = (blockIdx.x - NGEMM) * blockDim.x + threadIdx.x;
        int stride = 2048 * blockDim.x;
        for (; i < n4; i += stride) {
            float4 v = w2src[i];
            __half2 h0 = __floats2half2_rn(v.x, v.y);
            __half2 h1 = __floats2half2_rn(v.z, v.w);
            uint2 o; o.x = *(uint32_t*)&h0; o.y = *(uint32_t*)&h1;
            dst[i] = o;
        }
        return;
    }

    constexpr int BM = 128, BK = 64;
    constexpr int NC = KDIM / BK;
    constexpr int ALD = 72, BLD = 136;
    constexpr int ABYTES = BM * ALD * 2;          // 18432
    constexpr int STAGE  = ABYTES + BK * BLD * 2; // 35840

    extern __shared__ __align__(16) char dsm[];

    const int tid = threadIdx.x, wid = tid >> 5, lane = tid & 31;
    const int bx = blockIdx.x % GRIDX, by = blockIdx.x / GRIDX;
    const int rowBase = by * BM, colBase = bx * 128;
    const int e = rowBase >> 10;
    const uint32_t sbase = s2u(dsm);
    const int wm = (wid & 3) * 32, wn = (wid >> 2) * 64;

    uint32_t a_soff[4], b_soff[4];
    const __half* a_gp[4];
    const __half* b_gp[4];
    {
        const __half* Ap = g_einh + (size_t)rowBase * KDIM;
        const __half* Bp = g_w1h + (size_t)e * KDIM * NDIM + colBase;
        #pragma unroll
        for (int i = 0; i < 4; i++) {
            int ch = tid + i * 256;
            int ar = ch >> 3, aq = ch & 7;
            a_soff[i] = ar * 144 + aq * 16;
            a_gp[i]   = Ap + (size_t)ar * KDIM + aq * 8;
            int br = ch >> 4, bq = ch & 15;
            b_soff[i] = ABYTES + br * 272 + bq * 16;
            b_gp[i]   = Bp + (size_t)br * NDIM + bq * 8;
        }
    }

    wmma::fragment<wmma::accumulator, 16, 16, 16, float> acc[2][4];
    #pragma unroll
    for (int i = 0; i < 2; i++)
        #pragma unroll
        for (int j = 0; j < 4; j++) wmma::fill_fragment(acc[i][j], 0.f);

    auto issue = [&](int s) {
        uint32_t sb = sbase + s * STAGE;
        #pragma unroll
        for (int i = 0; i < 4; i++) CP16(sb + a_soff[i], a_gp[i]);
        #pragma unroll
        for (int i = 0; i < 4; i++) CP16(sb + b_soff[i], b_gp[i]);
        #pragma unroll
        for (int i = 0; i < 4; i++) { a_gp[i] += BK; b_gp[i] += (size_t)BK * NDIM; }
    };

    issue(0); CP_COMMIT();
    issue(1); CP_COMMIT();

    for (int c = 0; c < NC; c++) {
        int stg = c % 3;
        CP_WAIT1();
        __syncthreads();
        if (c + 2 < NC) issue((c + 2) % 3);
        CP_COMMIT();

        const __half* As_ = (const __half*)(dsm + stg * STAGE);
        const __half* Bs_ = (const __half*)(dsm + stg * STAGE + ABYTES);
        #pragma unroll
        for (int kk = 0; kk < 4; kk++) {
            wmma::fragment<wmma::matrix_a, 16, 16, 16, half, wmma::row_major> af[2];
            wmma::fragment<wmma::matrix_b, 16, 16, 16, half, wmma::row_major> bf[4];
            wmma::load_matrix_sync(af[0], As_ + (wm     ) * ALD + kk * 16, ALD);
            wmma::load_matrix_sync(af[1], As_ + (wm + 16) * ALD + kk * 16, ALD);
            #pragma unroll
            for (int j = 0; j < 4; j++)
                wmma::load_matrix_sync(bf[j], Bs_ + (kk * 16) * BLD + wn + j * 16, BLD);
            #pragma unroll
            for (int i = 0; i < 2; i++)
                #pragma unroll
                for (int j = 0; j < 4; j++)
                    wmma::mma_sync(acc[i][j], af[i], bf[j], acc[i][j]);
        }
    }
    __syncthreads();

    // epilogue: bias + exact GELU -> fp16 hidh
    float* epi = (float*)dsm + wid * 16 * 68;
    #pragma unroll
    for (int i = 0; i < 2; i++) {
        #pragma unroll
        for (int j = 0; j < 4; j++)
            wmma::store_matrix_sync(epi + j * 16, acc[i][j], 68, wmma::mem_row_major);
        __syncwarp();
        int r0 = rowBase + wm + i * 16;
        int c0 = colBase + wn;
        #pragma unroll
        for (int q = 0; q < 4; q++) {
            int sid = q * 32 + lane;
            int row = sid >> 3, c8 = (sid & 7) * 8;
            float4 b0 = *(const float4*)(&bias[c0 + c8]);
            float4 b1 = *(const float4*)(&bias[c0 + c8 + 4]);
            const float* er = epi + row * 68 + c8;
            float v0 = gelu_exact(er[0] + b0.x), v1 = gelu_exact(er[1] + b0.y);
            float v2 = gelu_exact(er[2] + b0.z), v3 = gelu_exact(er[3] + b0.w);
            float v4 = gelu_exact(er[4] + b1.x), v5 = gelu_exact(er[5] + b1.y);
            float v6 = gelu_exact(er[6] + b1.z), v7 = gelu_exact(er[7] + b1.w);
            __half2 h0 = __floats2half2_rn(v0, v1), h1 = __floats2half2_rn(v2, v3);
            __half2 h2 = __floats2half2_rn(v4, v5), h3 = __floats2half2_rn(v6, v7);
            uint4 o; o.x = *(uint32_t*)&h0; o.y = *(uint32_t*)&h1;
            o.z = *(uint32_t*)&h2; o.w = *(uint32_t*)&h3;
            *(uint4*)(&g_hidh[(size_t)(r0 + row) * NDIM + c0 + c8]) = o;
        }
        __syncwarp();
    }
}

// ------------- GEMM2: split-K=2, fp32 partials (no bias/act) -----------------
// grid (DIMM/128, NSLOT/128, 2); each z-half sums K in [z*2048, (z+1)*2048)
__global__ void __launch_bounds__(256, 2) hgemm2(int dummy) {
    constexpr int KDIM = HID, NDIM = DIMM;
    constexpr int KHALF = KDIM / 2;
    constexpr int BM = 128, BK = 64;
    constexpr int NC = KHALF / BK;                // 32
    constexpr int ALD = 72, BLD = 136;
    constexpr int ABYTES = BM * ALD * 2;
    constexpr int STAGE  = ABYTES + BK * BLD * 2;

    extern __shared__ __align__(16) char dsm[];

    const int tid = threadIdx.x, wid = tid >> 5, lane = tid & 31;
    const int bx = blockIdx.x, by = blockIdx.y, bz = blockIdx.z;
    const int rowBase = by * BM, colBase = bx * 128;
    const int e = rowBase >> 10;
    const int koff = bz * KHALF;
    const uint32_t sbase = s2u(dsm);
    const int wm = (wid & 3) * 32, wn = (wid >> 2) * 64;

    uint32_t a_soff[4], b_soff[4];
    const __half* a_gp[4];
    const __half* b_gp[4];
    {
        const __half* Ap = g_hidh + (size_t)rowBase * KDIM + koff;
        const __half* Bp = g_w2h + (size_t)e * KDIM * NDIM
                         + (size_t)koff * NDIM + colBase;
        #pragma unroll
        for (int i = 0; i < 4; i++) {
            int ch = tid + i * 256;
            int ar = ch >> 3, aq = ch & 7;
            a_soff[i] = ar * 144 + aq * 16;
            a_gp[i]   = Ap + (size_t)ar * KDIM + aq * 8;
            int br = ch >> 4, bq = ch & 15;
            b_soff[i] = ABYTES + br * 272 + bq * 16;
            b_gp[i]   = Bp + (size_t)br * NDIM + bq * 8;
        }
    }

    wmma::fragment<wmma::accumulator, 16, 16, 16, float> acc[2][4];
    #pragma unroll
    for (int i = 0; i < 2; i++)
        #pragma unroll
        for (int j = 0; j < 4; j++) wmma::fill_fragment(acc[i][j], 0.f);

    auto issue = [&](int s) {
        uint32_t sb = sbase + s * STAGE;
        #pragma unroll
        for (int i = 0; i < 4; i++) CP16(sb + a_soff[i], a_gp[i]);
        #pragma unroll
        for (int i = 0; i < 4; i++) CP16(sb + b_soff[i], b_gp[i]);
        #pragma unroll
        for (int i = 0; i < 4; i++) { a_gp[i] += BK; b_gp[i] += (size_t)BK * NDIM; }
    };

    issue(0); CP_COMMIT();
    issue(1); CP_COMMIT();

    for (int c = 0; c < NC; c++) {
        int stg = c % 3;
        CP_WAIT1();
        __syncthreads();
        if (c + 2 < NC) issue((c + 2) % 3);
        CP_COMMIT();

        const __half* As_ = (const __half*)(dsm + stg * STAGE);
        const __half* Bs_ = (const __half*)(dsm + stg * STAGE + ABYTES);
        #pragma unroll
        for (int kk = 0; kk < 4; kk++) {
            wmma::fragment<wmma::matrix_a, 16, 16, 16, half, wmma::row_major> af[2];
            wmma::fragment<wmma::matrix_b, 16, 16, 16, half, wmma::row_major> bf[4];
            wmma::load_matrix_sync(af[0], As_ + (wm     ) * ALD + kk * 16, ALD);
            wmma::load_matrix_sync(af[1], As_ + (wm + 16) * ALD + kk * 16, ALD);
            #pragma unroll
            for (int j = 0; j < 4; j++)
                wmma::load_matrix_sync(bf[j], Bs_ + (kk * 16) * BLD + wn + j * 16, BLD);
            #pragma unroll
            for (int i = 0; i < 2; i++)
                #pragma unroll
                for (int j = 0; j < 4; j++)
                    wmma::mma_sync(acc[i][j], af[i], bf[j], acc[i][j]);
        }
    }
    __syncthreads();

    // epilogue: raw fp32 partials
    float* __restrict__ P = g_pout + (size_t)bz * NSLOT * DIMM;
    float* epi = (float*)dsm + wid * 16 * 68;
    #pragma unroll
    for (int i = 0; i < 2; i++) {
        #pragma unroll
        for (int j = 0; j < 4; j++)
            wmma::store_matrix_sync(epi + j * 16, acc[i][j], 68, wmma::mem_row_major);
        __syncwarp();
        int r0 = rowBase + wm + i * 16;
        int c0 = colBase + wn;
        #pragma unroll
        for (int q = 0; q < 8; q++) {
            int sid = q * 32 + lane;
            int row = sid >> 4, c4 = (sid & 15) * 4;
            const float* er = epi + row * 68 + c4;
            float4 v; v.x = er[0]; v.y = er[1]; v.z = er[2]; v.w = er[3];
            *(float4*)(&P[(size_t)(r0 + row) * NDIM + c0 + c4]) = v;
        }
        __syncwarp();
    }
}

// ---------------- combine: g1*(p0+p1+b2) + g2*(p0+p1+b2) ---------------------
__global__ void combine_kernel(float* __restrict__ out,
                               const float* __restrict__ b2) {
    int tok = blockIdx.x;
    int t   = threadIdx.x;                         // 256 threads x 4 floats
    int s1 = g_slot1[tok], s2 = g_slot2[tok];
    float g1 = (s1 >= 0) ? g_g1[tok] : 0.f;
    float g2 = (s2 >= 0) ? g_g2[tok] : 0.f;
    float4 bv = ((const float4*)b2)[t];
    float4 v = make_float4(0.f, 0.f, 0.f, 0.f);
    const float* P0 = g_pout;
    const float* P1 = g_pout + (size_t)NSLOT * DIMM;
    if (s1 >= 0) {
        float4 a = ((const float4*)(P0 + (size_t)s1 * DIMM))[t];
        float4 b = ((const float4*)(P1 + (size_t)s1 * DIMM))[t];
        v.x += g1 * (a.x + b.x + bv.x); v.y += g1 * (a.y + b.y + bv.y);
        v.z += g1 * (a.z + b.z + bv.z); v.w += g1 * (a.w + b.w + bv.w);
    }
    if (s2 >= 0) {
        float4 a = ((const float4*)(P0 + (size_t)s2 * DIMM))[t];
        float4 b = ((const float4*)(P1 + (size_t)s2 * DIMM))[t];
        v.x += g2 * (a.x + b.x + bv.x); v.y += g2 * (a.y + b.y + bv.y);
        v.z += g2 * (a.z + b.z + bv.z); v.w += g2 * (a.w + b.w + bv.w);
    }
    ((float4*)(out + (size_t)tok * DIMM))[t] = v;
}

// -------------------------------- loss ---------------------------------------
__global__ void loss_part_kernel() {
    int be = blockIdx.x;
    int b = be / NE, e = be % NE;
    __shared__ float s[256];
    float acc = 0.f;
    for (int n = threadIdx.x; n < NN; n += 256)
        acc += g_probs[(size_t)(b * NN + n) * NE + e];
    s[threadIdx.x] = acc; __syncthreads();
    for (int off = 128; off; off >>= 1) {
        if (threadIdx.x < off) s[threadIdx.x] += s[threadIdx.x + off];
        __syncthreads();
    }
    if (threadIdx.x == 0)
        g_part_loss[be] = (s[0] / (float)NN) *
                          ((float)g_cnt_total[be] / (float)NN);
}

__global__ void loss_final_kernel(float* __restrict__ out) {
    __shared__ float s[64];
    int t = threadIdx.x;
    s[t] = g_part_loss[t]; __syncthreads();
    for (int off = 32; off; off >>= 1) {
        if (t < off) s[t] += s[t + off];
        __syncthreads();
    }
    if (t == 0) out[(size_t)NTOK * DIMM] = s[0] * 0.04f;
}

// ------------------------------- launch --------------------------------------
extern "C" void kernel_launch(void* const* d_in, const int* in_sizes, int n_in,
                              void* d_out, int out_size) {
    const float* x  = (const float*)d_in[0];
    const float* wg = (const float*)d_in[1];
    const float* w1 = (const float*)d_in[2];
    const float* w2 = (const float*)d_in[3];
    const float* b1 = (const float*)d_in[4];
    const float* b2 = (const float*)d_in[5];
    float* out = (float*)d_out;

    constexpr int SMEM = 3 * 35840;   // 107520
    cudaFuncSetAttribute(hgemm1,
                         cudaFuncAttributeMaxDynamicSharedMemorySize, SMEM);
    cudaFuncSetAttribute(hgemm2,
                         cudaFuncAttributeMaxDynamicSharedMemorySize, SMEM);

    const int W4 = NE * DIMM * HID / 4;
    gating_wconv1_kernel<<<NTOK + 4096, 512>>>(x, wg, (const float4*)w1, W4); // 0
    assign_kernel<<<BB * NE, 256>>>();                                        // 1
    gather_kernel<<<NSLOT, 256>>>(x);                                         // 2
    hgemm1<<<(HID / 128) * (NSLOT / 128) + 2048, 256, SMEM>>>(
        b1, (const float4*)w2, W4);                                           // 3
    hgemm2<<<dim3(DIMM / 128, NSLOT / 128, 2), 256, SMEM>>>(0);               // 4
    combine_kernel<<<NTOK, 256>>>(out, b2);                                   // 5
    loss_part_kernel<<<BB * NE, 256>>>();                                     // 6
    if (out_size > NTOK * DIMM)
        loss_final_kernel<<<1, 64>>>(out);                                    // 7
}

// round 17
// speedup vs baseline: 1.0100x; 1.0100x over previous
#include <cuda_runtime.h>
#include <cuda_fp16.h>
#include <mma.h>
#include <math.h>
#include <stdint.h>

#define BB   4
#define NN   2048
#define DIMM 1024
#define HID  4096
#define NE   16
#define CAP  256
#define NTOK (BB*NN)          // 8192 tokens
#define NSLOT (NE*BB*CAP)     // 16384 expert slot rows
#define FLT_MIN_NORM 1.17549435e-38f
#define EXP_FTZ_CUT  (-87.336544f)

using namespace nvcuda;

// ------------------------- scratch (device globals) -------------------------
__device__ float  g_probs[NTOK*NE];
__device__ int    g_e1[NTOK], g_e2[NTOK];
__device__ float  g_g1[NTOK], g_g2[NTOK];
__device__ int    g_slot1[NTOK], g_slot2[NTOK];
__device__ int    g_slot_token[NSLOT];
__device__ int    g_cnt_total[BB*NE];
__device__ float  g_part_loss[BB*NE];
__device__ __half g_einh [(size_t)NSLOT*DIMM];       // 32 MB
__device__ __half g_hidh [(size_t)NSLOT*HID];        // 128 MB
__device__ __half g_eouth[(size_t)NSLOT*DIMM];       // 32 MB
__device__ __half g_w1h  [(size_t)NE*DIMM*HID];      // 128 MB
__device__ __half g_w2h  [(size_t)NE*HID*DIMM];      // 128 MB

// ------------------------- async-copy helpers --------------------------------
__device__ __forceinline__ uint32_t s2u(const void* p) {
    uint32_t a;
    asm("{ .reg .u64 t; cvta.to.shared.u64 t, %1; cvt.u32.u64 %0, t; }"
        : "=r"(a) : "l"(p));
    return a;
}
#define CP16(dst, src) \
    asm volatile("cp.async.cg.shared.global [%0], [%1], 16;" \
                 :: "r"(dst), "l"(src) : "memory")
#define CP_COMMIT() asm volatile("cp.async.commit_group;" ::: "memory")
#define CP_WAIT1()  asm volatile("cp.async.wait_group 1;" ::: "memory")

// -------------------- gating + fused w1 conversion ---------------------------
// blocks [0, NTOK)          : gating (x row staged in smem; FTZ tail GOLDEN)
// blocks [NTOK, NTOK+4096)  : w1 fp32 -> fp16 (overlaps gating)
__global__ void gating_wconv1_kernel(const float* __restrict__ x,
                                     const float* __restrict__ wg,
                                     const float4* __restrict__ w1src, int n4) {
    if (blockIdx.x >= NTOK) {
        uint2* __restrict__ dst = (uint2*)g_w1h;
        int i = (blockIdx.x - NTOK) * blockDim.x + threadIdx.x;
        int stride = 4096 * blockDim.x;
        for (; i < n4; i += stride) {
            float4 v = w1src[i];
            __half2 h0 = __floats2half2_rn(v.x, v.y);
            __half2 h1 = __floats2half2_rn(v.z, v.w);
            uint2 o; o.x = *(uint32_t*)&h0; o.y = *(uint32_t*)&h1;
            dst[i] = o;
        }
        return;
    }

    int tok  = blockIdx.x;
    int wid  = threadIdx.x >> 5;        // expert
    int lane = threadIdx.x & 31;

    // stage the x row ONCE (kills the 16x redundant row reads)
    __shared__ __align__(16) float xs[DIMM];
    if (threadIdx.x < 256)
        ((float4*)xs)[threadIdx.x] =
            ((const float4*)(x + (size_t)tok * DIMM))[threadIdx.x];
    __syncthreads();

    float acc = 0.f;
    #pragma unroll 8
    for (int d = lane; d < DIMM; d += 32)
        acc = fmaf(xs[d], wg[d * NE + wid], acc);
    #pragma unroll
    for (int o = 16; o; o >>= 1) acc += __shfl_xor_sync(0xffffffffu, acc, o);

    __shared__ float lg[NE];
    if (lane == 0) lg[wid] = acc;
    __syncthreads();

    if (threadIdx.x == 0) {
        float l[NE], p[NE];
        #pragma unroll
        for (int i = 0; i < NE; i++) l[i] = lg[i];

        float m = l[0];
        #pragma unroll
        for (int i = 1; i < NE; i++) m = fmaxf(m, l[i]);
        float s = 0.f;
        #pragma unroll
        for (int i = 0; i < NE; i++) {
            float t = l[i] - m;
            float pe = (t < EXP_FTZ_CUT) ? 0.f : expf(t);   // FTZ exp
            p[i] = pe; s = s + pe;
        }
        #pragma unroll
        for (int i = 0; i < NE; i++) {
            float q = p[i] / s;
            if (q < FLT_MIN_NORM) q = 0.f;                  // FTZ divide
            p[i] = q;
        }

        int i1 = 0; float p1 = p[0];
        #pragma unroll
        for (int i = 1; i < NE; i++) if (p[i] > p1) { p1 = p[i]; i1 = i; }
        float gw[NE];
        #pragma unroll
        for (int i = 0; i < NE; i++) gw[i] = (i == i1) ? 0.f : p[i];
        int i2 = 0; float p2v = gw[0];
        #pragma unroll
        for (int i = 1; i < NE; i++) if (gw[i] > p2v) { p2v = gw[i]; i2 = i; }

        float den = p1 + p2v + 1e-9f;
        g_e1[tok] = i1; g_e2[tok] = i2;
        g_g1[tok] = p1 / den; g_g2[tok] = p2v / den;
        #pragma unroll
        for (int i = 0; i < NE; i++) g_probs[tok * NE + i] = p[i];
    }
}

// ---------------- capacity / assign (slot-segment clear fused in) ------------
__global__ void assign_kernel() {
    const int T = 256, TPT = NN / T;
    int b = blockIdx.x / NE, e = blockIdx.x % NE;
    int t = threadIdx.x;
    __shared__ int s[T];

    g_slot_token[(e * BB + b) * CAP + t] = -1;
    __syncthreads();

    int flag[TPT], loc[TPT]; int c = 0;
    #pragma unroll
    for (int i = 0; i < TPT; i++) {
        int n = t * TPT + i;
        int f = (g_e1[b * NN + n] == e);
        flag[i] = f; loc[i] = c; c += f;
    }
    s[t] = c; __syncthreads();
    for (int off = 1; off < T; off <<= 1) {
        int v = (t >= off) ? s[t - off] : 0;
        __syncthreads(); s[t] += v; __syncthreads();
    }
    int total = s[T - 1];
    int excl  = s[t] - c;
    #pragma unroll
    for (int i = 0; i < TPT; i++) {
        if (flag[i]) {
            int n = t * TPT + i, gi = b * NN + n;
            int pos = excl + loc[i];
            if (pos < CAP) {
                int slot = (e * BB + b) * CAP + pos;
                g_slot1[gi] = slot;
                g_slot_token[slot] = gi;
            } else g_slot1[gi] = -1;
        }
    }
    if (t == 0) g_cnt_total[b * NE + e] = total;
    int kept1 = total < CAP ? total : CAP;
    __syncthreads();

    c = 0;
    #pragma unroll
    for (int i = 0; i < TPT; i++) {
        int n = t * TPT + i;
        int f = (g_e2[b * NN + n] == e);
        flag[i] = f; loc[i] = c; c += f;
    }
    s[t] = c; __syncthreads();
    for (int off = 1; off < T; off <<= 1) {
        int v = (t >= off) ? s[t - off] : 0;
        __syncthreads(); s[t] += v; __syncthreads();
    }
    excl = s[t] - c;
    #pragma unroll
    for (int i = 0; i < TPT; i++) {
        if (flag[i]) {
            int n = t * TPT + i, gi = b * NN + n;
            int pos = excl + loc[i] + kept1;
            if (pos < CAP) {
                int slot = (e * BB + b) * CAP + pos;
                g_slot2[gi] = slot;
                g_slot_token[slot] = gi;
            } else g_slot2[gi] = -1;
        }
    }
}

// ------------------------------- gather (fp32 -> fp16) -----------------------
__global__ void gather_kernel(const float* __restrict__ x) {
    int row = blockIdx.x;
    int tok = g_slot_token[row];
    uint2* dst = (uint2*)(g_einh + (size_t)row * DIMM);
    int t = threadIdx.x;
    if (tok >= 0) {
        float4 v = ((const float4*)(x + (size_t)tok * DIMM))[t];
        __half2 h0 = __floats2half2_rn(v.x, v.y);
        __half2 h1 = __floats2half2_rn(v.z, v.w);
        uint2 o; o.x = *(uint32_t*)&h0; o.y = *(uint32_t*)&h1;
        dst[t] = o;
    } else {
        dst[t] = make_uint2(0u, 0u);
    }
}

__device__ __forceinline__ float gelu_exact(float v) {
    return 0.5f * v * (1.f + erff(v * 0.70710678118654752f));
}

// ---------------- GEMM1: 128x128x64, 3-stage, +fused wconv2 ------------------
__global__ void __launch_bounds__(256, 2) hgemm1(const float* __restrict__ bias,
                                                 const float4* __restrict__ w2src,
                                                 int n4) {
    constexpr int KDIM = DIMM, NDIM = HID;
    constexpr int GRIDX = NDIM / 128;
    constexpr int NGEMM = GRIDX * (NSLOT / 128);

    if (blockIdx.x >= NGEMM) {
        uint2* __restrict__ dst = (uint2*)g_w2h;
        int i = (blockIdx.x - NGEMM) * blockDim.x + threadIdx.x;
        int stride = 2048 * blockDim.x;
        for (; i < n4; i += stride) {
            float4 v = w2src[i];
            __half2 h0 = __floats2half2_rn(v.x, v.y);
            __half2 h1 = __floats2half2_rn(v.z, v.w);
            uint2 o; o.x = *(uint32_t*)&h0; o.y = *(uint32_t*)&h1;
            dst[i] = o;
        }
        return;
    }

    constexpr int BM = 128, BK = 64;
    constexpr int NC = KDIM / BK;
    constexpr int ALD = 72, BLD = 136;
    constexpr int ABYTES = BM * ALD * 2;          // 18432
    constexpr int STAGE  = ABYTES + BK * BLD * 2; // 35840

    extern __shared__ __align__(16) char dsm[];

    const int tid = threadIdx.x, wid = tid >> 5, lane = tid & 31;
    const int bx = blockIdx.x % GRIDX, by = blockIdx.x / GRIDX;
    const int rowBase = by * BM, colBase = bx * 128;
    const int e = rowBase >> 10;
    const uint32_t sbase = s2u(dsm);
    const int wm = (wid & 3) * 32, wn = (wid >> 2) * 64;

    uint32_t a_soff[4], b_soff[4];
    const __half* a_gp[4];
    const __half* b_gp[4];
    {
        const __half* Ap = g_einh + (size_t)rowBase * KDIM;
        const __half* Bp = g_w1h + (size_t)e * KDIM * NDIM + colBase;
        #pragma unroll
        for (int i = 0; i < 4; i++) {
            int ch = tid + i * 256;
            int ar = ch >> 3, aq = ch & 7;
            a_soff[i] = ar * 144 + aq * 16;
            a_gp[i]   = Ap + (size_t)ar * KDIM + aq * 8;
            int br = ch >> 4, bq = ch & 15;
            b_soff[i] = ABYTES + br * 272 + bq * 16;
            b_gp[i]   = Bp + (size_t)br * NDIM + bq * 8;
        }
    }

    wmma::fragment<wmma::accumulator, 16, 16, 16, float> acc[2][4];
    #pragma unroll
    for (int i = 0; i < 2; i++)
        #pragma unroll
        for (int j = 0; j < 4; j++) wmma::fill_fragment(acc[i][j], 0.f);

    auto issue = [&](int s) {
        uint32_t sb = sbase + s * STAGE;
        #pragma unroll
        for (int i = 0; i < 4; i++) CP16(sb + a_soff[i], a_gp[i]);
        #pragma unroll
        for (int i = 0; i < 4; i++) CP16(sb + b_soff[i], b_gp[i]);
        #pragma unroll
        for (int i = 0; i < 4; i++) { a_gp[i] += BK; b_gp[i] += (size_t)BK * NDIM; }
    };

    issue(0); CP_COMMIT();
    issue(1); CP_COMMIT();

    for (int c = 0; c < NC; c++) {
        int stg = c % 3;
        CP_WAIT1();
        __syncthreads();
        if (c + 2 < NC) issue((c + 2) % 3);
        CP_COMMIT();

        const __half* As_ = (const __half*)(dsm + stg * STAGE);
        const __half* Bs_ = (const __half*)(dsm + stg * STAGE + ABYTES);
        #pragma unroll
        for (int kk = 0; kk < 4; kk++) {
            wmma::fragment<wmma::matrix_a, 16, 16, 16, half, wmma::row_major> af[2];
            wmma::fragment<wmma::matrix_b, 16, 16, 16, half, wmma::row_major> bf[4];
            wmma::load_matrix_sync(af[0], As_ + (wm     ) * ALD + kk * 16, ALD);
            wmma::load_matrix_sync(af[1], As_ + (wm + 16) * ALD + kk * 16, ALD);
            #pragma unroll
            for (int j = 0; j < 4; j++)
                wmma::load_matrix_sync(bf[j], Bs_ + (kk * 16) * BLD + wn + j * 16, BLD);
            #pragma unroll
            for (int i = 0; i < 2; i++)
                #pragma unroll
                for (int j = 0; j < 4; j++)
                    wmma::mma_sync(acc[i][j], af[i], bf[j], acc[i][j]);
        }
    }
    __syncthreads();

    // epilogue: bias + exact GELU -> fp16 hidh
    float* epi = (float*)dsm + wid * 16 * 68;
    #pragma unroll
    for (int i = 0; i < 2; i++) {
        #pragma unroll
        for (int j = 0; j < 4; j++)
            wmma::store_matrix_sync(epi + j * 16, acc[i][j], 68, wmma::mem_row_major);
        __syncwarp();
        int r0 = rowBase + wm + i * 16;
        int c0 = colBase + wn;
        #pragma unroll
        for (int q = 0; q < 4; q++) {
            int sid = q * 32 + lane;
            int row = sid >> 3, c8 = (sid & 7) * 8;
            float4 b0 = *(const float4*)(&bias[c0 + c8]);
            float4 b1 = *(const float4*)(&bias[c0 + c8 + 4]);
            const float* er = epi + row * 68 + c8;
            float v0 = gelu_exact(er[0] + b0.x), v1 = gelu_exact(er[1] + b0.y);
            float v2 = gelu_exact(er[2] + b0.z), v3 = gelu_exact(er[3] + b0.w);
            float v4 = gelu_exact(er[4] + b1.x), v5 = gelu_exact(er[5] + b1.y);
            float v6 = gelu_exact(er[6] + b1.z), v7 = gelu_exact(er[7] + b1.w);
            __half2 h0 = __floats2half2_rn(v0, v1), h1 = __floats2half2_rn(v2, v3);
            __half2 h2 = __floats2half2_rn(v4, v5), h3 = __floats2half2_rn(v6, v7);
            uint4 o; o.x = *(uint32_t*)&h0; o.y = *(uint32_t*)&h1;
            o.z = *(uint32_t*)&h2; o.w = *(uint32_t*)&h3;
            *(uint4*)(&g_hidh[(size_t)(r0 + row) * NDIM + c0 + c8]) = o;
        }
        __syncwarp();
    }
}

// ---------------- GEMM2: 128x128x64, 3-stage, bias, fp16 out -----------------
__global__ void __launch_bounds__(256, 2) hgemm2(const float* __restrict__ bias) {
    constexpr int KDIM = HID, NDIM = DIMM;
    constexpr int GRIDX = NDIM / 128;
    constexpr int BM = 128, BK = 64;
    constexpr int NC = KDIM / BK;
    constexpr int ALD = 72, BLD = 136;
    constexpr int ABYTES = BM * ALD * 2;
    constexpr int STAGE  = ABYTES + BK * BLD * 2;

    extern __shared__ __align__(16) char dsm[];

    const int tid = threadIdx.x, wid = tid >> 5, lane = tid & 31;
    const int bx = blockIdx.x % GRIDX, by = blockIdx.x / GRIDX;
    const int rowBase = by * BM, colBase = bx * 128;
    const int e = rowBase >> 10;
    const uint32_t sbase = s2u(dsm);
    const int wm = (wid & 3) * 32, wn = (wid >> 2) * 64;

    uint32_t a_soff[4], b_soff[4];
    const __half* a_gp[4];
    const __half* b_gp[4];
    {
        const __half* Ap = g_hidh + (size_t)rowBase * KDIM;
        const __half* Bp = g_w2h + (size_t)e * KDIM * NDIM + colBase;
        #pragma unroll
        for (int i = 0; i < 4; i++) {
            int ch = tid + i * 256;
            int ar = ch >> 3, aq = ch & 7;
            a_soff[i] = ar * 144 + aq * 16;
            a_gp[i]   = Ap + (size_t)ar * KDIM + aq * 8;
            int br = ch >> 4, bq = ch & 15;
            b_soff[i] = ABYTES + br * 272 + bq * 16;
            b_gp[i]   = Bp + (size_t)br * NDIM + bq * 8;
        }
    }

    wmma::fragment<wmma::accumulator, 16, 16, 16, float> acc[2][4];
    #pragma unroll
    for (int i = 0; i < 2; i++)
        #pragma unroll
        for (int j = 0; j < 4; j++) wmma::fill_fragment(acc[i][j], 0.f);

    auto issue = [&](int s) {
        uint32_t sb = sbase + s * STAGE;
        #pragma unroll
        for (int i = 0; i < 4; i++) CP16(sb + a_soff[i], a_gp[i]);
        #pragma unroll
        for (int i = 0; i < 4; i++) CP16(sb + b_soff[i], b_gp[i]);
        #pragma unroll
        for (int i = 0; i < 4; i++) { a_gp[i] += BK; b_gp[i] += (size_t)BK * NDIM; }
    };

    issue(0); CP_COMMIT();
    issue(1); CP_COMMIT();

    for (int c = 0; c < NC; c++) {
        int stg = c % 3;
        CP_WAIT1();
        __syncthreads();
        if (c + 2 < NC) issue((c + 2) % 3);
        CP_COMMIT();

        const __half* As_ = (const __half*)(dsm + stg * STAGE);
        const __half* Bs_ = (const __half*)(dsm + stg * STAGE + ABYTES);
        #pragma unroll
        for (int kk = 0; kk < 4; kk++) {
            wmma::fragment<wmma::matrix_a, 16, 16, 16, half, wmma::row_major> af[2];
            wmma::fragment<wmma::matrix_b, 16, 16, 16, half, wmma::row_major> bf[4];
            wmma::load_matrix_sync(af[0], As_ + (wm     ) * ALD + kk * 16, ALD);
            wmma::load_matrix_sync(af[1], As_ + (wm + 16) * ALD + kk * 16, ALD);
            #pragma unroll
            for (int j = 0; j < 4; j++)
                wmma::load_matrix_sync(bf[j], Bs_ + (kk * 16) * BLD + wn + j * 16, BLD);
            #pragma unroll
            for (int i = 0; i < 2; i++)
                #pragma unroll
                for (int j = 0; j < 4; j++)
                    wmma::mma_sync(acc[i][j], af[i], bf[j], acc[i][j]);
        }
    }
    __syncthreads();

    // epilogue: bias (no act) -> fp16 eouth
    float* epi = (float*)dsm + wid * 16 * 68;
    #pragma unroll
    for (int i = 0; i < 2; i++) {
        #pragma unroll
        for (int j = 0; j < 4; j++)
            wmma::store_matrix_sync(epi + j * 16, acc[i][j], 68, wmma::mem_row_major);
        __syncwarp();
        int r0 = rowBase + wm + i * 16;
        int c0 = colBase + wn;
        #pragma unroll
        for (int q = 0; q < 4; q++) {
            int sid = q * 32 + lane;
            int row = sid >> 3, c8 = (sid & 7) * 8;
            float4 b0 = *(const float4*)(&bias[c0 + c8]);
            float4 b1 = *(const float4*)(&bias[c0 + c8 + 4]);
            const float* er = epi + row * 68 + c8;
            float v0 = er[0] + b0.x, v1 = er[1] + b0.y;
            float v2 = er[2] + b0.z, v3 = er[3] + b0.w;
            float v4 = er[4] + b1.x, v5 = er[5] + b1.y;
            float v6 = er[6] + b1.z, v7 = er[7] + b1.w;
            __half2 h0 = __floats2half2_rn(v0, v1), h1 = __floats2half2_rn(v2, v3);
            __half2 h2 = __floats2half2_rn(v4, v5), h3 = __floats2half2_rn(v6, v7);
            uint4 o; o.x = *(uint32_t*)&h0; o.y = *(uint32_t*)&h1;
            o.z = *(uint32_t*)&h2; o.w = *(uint32_t*)&h3;
            *(uint4*)(&g_eouth[(size_t)(r0 + row) * NDIM + c0 + c8]) = o;
        }
        __syncwarp();
    }
}

// ------------------------------- combine (fp16 eout) -------------------------
__global__ void combine_kernel(float* __restrict__ out) {
    int tok = blockIdx.x;
    int t   = threadIdx.x;                         // 256 threads x 4 floats
    int s1 = g_slot1[tok], s2 = g_slot2[tok];
    float g1 = (s1 >= 0) ? g_g1[tok] : 0.f;
    float g2 = (s2 >= 0) ? g_g2[tok] : 0.f;
    float4 v = make_float4(0.f, 0.f, 0.f, 0.f);
    if (s1 >= 0) {
        uint2 raw = ((const uint2*)(g_eouth + (size_t)s1 * DIMM))[t];
        float2 a0 = __half22float2(*(__half2*)&raw.x);
        float2 a1 = __half22float2(*(__half2*)&raw.y);
        v.x += g1 * a0.x; v.y += g1 * a0.y; v.z += g1 * a1.x; v.w += g1 * a1.y;
    }
    if (s2 >= 0) {
        uint2 raw = ((const uint2*)(g_eouth + (size_t)s2 * DIMM))[t];
        float2 a0 = __half22float2(*(__half2*)&raw.x);
        float2 a1 = __half22float2(*(__half2*)&raw.y);
        v.x += g2 * a0.x; v.y += g2 * a0.y; v.z += g2 * a1.x; v.w += g2 * a1.y;
    }
    ((float4*)(out + (size_t)tok * DIMM))[t] = v;
}

// -------------------------------- loss ---------------------------------------
__global__ void loss_part_kernel() {
    int be = blockIdx.x;
    int b = be / NE, e = be % NE;
    __shared__ float s[256];
    float acc = 0.f;
    for (int n = threadIdx.x; n < NN; n += 256)
        acc += g_probs[(size_t)(b * NN + n) * NE + e];
    s[threadIdx.x] = acc; __syncthreads();
    for (int off = 128; off; off >>= 1) {
        if (threadIdx.x < off) s[threadIdx.x] += s[threadIdx.x + off];
        __syncthreads();
    }
    if (threadIdx.x == 0)
        g_part_loss[be] = (s[0] / (float)NN) *
                          ((float)g_cnt_total[be] / (float)NN);
}

__global__ void loss_final_kernel(float* __restrict__ out) {
    __shared__ float s[64];
    int t = threadIdx.x;
    s[t] = g_part_loss[t]; __syncthreads();
    for (int off = 32; off; off >>= 1) {
        if (t < off) s[t] += s[t + off];
        __syncthreads();
    }
    if (t == 0) out[(size_t)NTOK * DIMM] = s[0] * 0.04f;
}

// ------------------------------- launch --------------------------------------
extern "C" void kernel_launch(void* const* d_in, const int* in_sizes, int n_in,
                              void* d_out, int out_size) {
    const float* x  = (const float*)d_in[0];
    const float* wg = (const float*)d_in[1];
    const float* w1 = (const float*)d_in[2];
    const float* w2 = (const float*)d_in[3];
    const float* b1 = (const float*)d_in[4];
    const float* b2 = (const float*)d_in[5];
    float* out = (float*)d_out;

    constexpr int SMEM = 3 * 35840;   // 107520
    cudaFuncSetAttribute(hgemm1,
                         cudaFuncAttributeMaxDynamicSharedMemorySize, SMEM);
    cudaFuncSetAttribute(hgemm2,
                         cudaFuncAttributeMaxDynamicSharedMemorySize, SMEM);

    const int W4 = NE * DIMM * HID / 4;
    gating_wconv1_kernel<<<NTOK + 4096, 512>>>(x, wg, (const float4*)w1, W4); // 0
    assign_kernel<<<BB * NE, 256>>>();                                        // 1
    gather_kernel<<<NSLOT, 256>>>(x);                                         // 2
    hgemm1<<<(HID / 128) * (NSLOT / 128) + 2048, 256, SMEM>>>(
        b1, (const float4*)w2, W4);                                           // 3
    hgemm2<<<(DIMM / 128) * (NSLOT / 128), 256, SMEM>>>(b2);                  // 4
    combine_kernel<<<NTOK, 256>>>(out);                                       // 5
    loss_part_kernel<<<BB * NE, 256>>>();                                     // 6
    if (out_size > NTOK * DIMM)
        loss_final_kernel<<<1, 64>>>(out);                                    // 7
}